// round 4
// baseline (speedup 1.0000x reference)
#include <cuda_runtime.h>
#include <cuda_fp16.h>

// WaterLevelLSTM via legacy tensor cores (mma.sync.m16n8k16 f16 -> f32).
// Per CTA: 128 batch rows. Per step, gates[128,256] = h[128,64] @ W_hh^T
// as MMA with 3-term fp16 split (h_hi*W_hi + h_hi*W_lo + h_lo*W_hi) for
// fp32-grade precision. D-fragment layout == A-fragment layout, so new h
// packs straight into next step's A registers: no SMEM h traffic and no
// __syncthreads in the time loop. W (fp16 hi/lo) in SMEM, c in registers.

#define TSTEPS 5
#define NTH    256
#define MT     128
#define ROWPAD 72            // halves per W row in smem (64 + 8 pad)

// smem byte offsets
#define SM_WHI  0
#define SM_WLO  36864        // 256*72*2
#define SM_X    73728        // 128*5 floats
#define SM_BIAS 76288        // 256 floats (b_ih+b_hh)
#define SM_WIH  77312        // 256 floats
#define SM_WFC  78336        // 64 floats
#define SM_SIZE 78592

typedef unsigned int u32;

__device__ __forceinline__ void mma16816(float* d, const u32* a, const u32* b) {
    asm volatile("mma.sync.aligned.m16n8k16.row.col.f32.f16.f16.f32 "
        "{%0,%1,%2,%3}, {%4,%5,%6,%7}, {%8,%9}, {%0,%1,%2,%3};"
        : "+f"(d[0]), "+f"(d[1]), "+f"(d[2]), "+f"(d[3])
        : "r"(a[0]), "r"(a[1]), "r"(a[2]), "r"(a[3]), "r"(b[0]), "r"(b[1]));
}
__device__ __forceinline__ void ldsm4(u32* r, u32 addr) {
    asm volatile("ldmatrix.sync.aligned.m8n8.x4.shared.b16 {%0,%1,%2,%3}, [%4];"
        : "=r"(r[0]), "=r"(r[1]), "=r"(r[2]), "=r"(r[3]) : "r"(addr));
}
__device__ __forceinline__ u32 s2u(const void* p) {
    u32 a;
    asm("{ .reg .u64 t; cvta.to.shared.u64 t, %1; cvt.u32.u64 %0, t; }"
        : "=r"(a) : "l"(p));
    return a;
}
__device__ __forceinline__ u32 packh2(float a, float b) {
    __half2 h = __floats2half2_rn(a, b);
    return *reinterpret_cast<u32*>(&h);
}
// accurate MUFU sigmoid/tanh (EX2 ~2^-22), not tanh.approx
__device__ __forceinline__ float sigf(float x) {
    return __fdividef(1.0f, 1.0f + __expf(-x));
}
__device__ __forceinline__ float tanhacc(float x) {
    return __fdividef(2.0f, 1.0f + __expf(-2.0f * x)) - 1.0f;
}

__global__ __launch_bounds__(NTH, 1)
void lstm_mma_kernel(const float* __restrict__ x,
                     const float* __restrict__ W_ih,
                     const float* __restrict__ W_hh,
                     const float* __restrict__ b_ih,
                     const float* __restrict__ b_hh,
                     const float* __restrict__ W_fc,
                     const float* __restrict__ b_fc,
                     float* __restrict__ out,
                     int B)
{
    extern __shared__ char smem[];
    const u32 sb = s2u(smem);
    const int tid  = threadIdx.x;
    const int warp = tid >> 5;
    const int lane = tid & 31;
    const int gid  = lane >> 2;      // row group within warp tile
    const int tig  = lane & 3;       // col group

    __half* whi = reinterpret_cast<__half*>(smem + SM_WHI);
    __half* wlo = reinterpret_cast<__half*>(smem + SM_WLO);
    float* x_s    = reinterpret_cast<float*>(smem + SM_X);
    float* bias_s = reinterpret_cast<float*>(smem + SM_BIAS);
    float* wih_s  = reinterpret_cast<float*>(smem + SM_WIH);
    float* wfc_s  = reinterpret_cast<float*>(smem + SM_WFC);

    // ---- prologue ----
    for (int i = tid; i < 256 * 64; i += NTH) {
        int n = i >> 6, k = i & 63;
        float w  = W_hh[i];
        __half hh = __float2half_rn(w);
        whi[n * ROWPAD + k] = hh;
        wlo[n * ROWPAD + k] = __float2half_rn(w - __half2float(hh));
    }
    if (tid < 256) {
        bias_s[tid] = b_ih[tid] + b_hh[tid];
        wih_s[tid]  = W_ih[tid];
    }
    if (tid < 64) wfc_s[tid] = W_fc[tid];
    {   // stage x for this CTA's 128 rows (coalesced)
        long base = (long)blockIdx.x * MT * TSTEPS;
        for (int i = tid; i < MT * TSTEPS; i += NTH) {
            long gidx = base + i;
            x_s[i] = (gidx < (long)B * TSTEPS) ? x[gidx] : 0.0f;
        }
    }
    __syncthreads();   // the only block-wide sync

    // ---- per-thread setup ----
    const int row0 = warp * 16 + gid;       // CTA-local rows
    const int row1 = row0 + 8;
    float xs0[TSTEPS], xs1[TSTEPS];
#pragma unroll
    for (int s = 0; s < TSTEPS; s++) {
        xs0[s] = x_s[row0 * TSTEPS + s];
        xs1[s] = x_s[row1 * TSTEPS + s];
    }
    const float bfc = b_fc[0];

    float c[32];                 // c[jg*4 + p]
#pragma unroll
    for (int i = 0; i < 32; i++) c[i] = 0.0f;

    u32 Ahi[2][4][4], Alo[2][4][4];   // [buf][kstep][frag]
    float oacc0 = 0.0f, oacc1 = 0.0f;

    const u32 whi_b = sb + SM_WHI;
    const u32 lmoff = (u32)((lane & 7) * (ROWPAD * 2) + (lane >> 3) * 16);

#pragma unroll
    for (int s = 0; s < TSTEPS; s++) {
        const int wr = s & 1;
        const int rd = wr ^ 1;

#pragma unroll
        for (int jg = 0; jg < 8; jg++) {
            float D[4][4];
#pragma unroll
            for (int ty = 0; ty < 4; ty++)
#pragma unroll
                for (int p = 0; p < 4; p++) D[ty][p] = 0.0f;

            if (s > 0) {
#pragma unroll
                for (int ty = 0; ty < 4; ty++) {
                    u32 rb = whi_b + (u32)((ty * 64 + jg * 8) * (ROWPAD * 2)) + lmoff;
                    u32 bh[8], bl[8];
                    ldsm4(bh + 0, rb);            // W_hi k[0,32)
                    ldsm4(bh + 4, rb + 64);       // W_hi k[32,64)
                    ldsm4(bl + 0, rb + SM_WLO);   // W_lo
                    ldsm4(bl + 4, rb + SM_WLO + 64);
#pragma unroll
                    for (int kk = 0; kk < 4; kk++) {
                        mma16816(D[ty], Ahi[rd][kk], bh + 2 * kk);
                        mma16816(D[ty], Alo[rd][kk], bh + 2 * kk);
                        mma16816(D[ty], Ahi[rd][kk], bl + 2 * kk);
                    }
                }
            }

            // ---- epilogue for this jg: 4 units (2 rows x 2 cols) ----
            const int cb = jg * 8 + 2 * tig;
            float2 biaI = *(const float2*)(bias_s + 0 * 64 + cb);
            float2 biaF = *(const float2*)(bias_s + 1 * 64 + cb);
            float2 biaG = *(const float2*)(bias_s + 2 * 64 + cb);
            float2 biaO = *(const float2*)(bias_s + 3 * 64 + cb);
            float2 wivI = *(const float2*)(wih_s + 0 * 64 + cb);
            float2 wivF = *(const float2*)(wih_s + 1 * 64 + cb);
            float2 wivG = *(const float2*)(wih_s + 2 * 64 + cb);
            float2 wivO = *(const float2*)(wih_s + 3 * 64 + cb);

            float hv[4];
#pragma unroll
            for (int p = 0; p < 4; p++) {
                const float xs = (p < 2) ? xs0[s] : xs1[s];
                const bool hi = (p & 1);
                float gI = D[0][p] + fmaf(xs, hi ? wivI.y : wivI.x, hi ? biaI.y : biaI.x);
                float gF = D[1][p] + fmaf(xs, hi ? wivF.y : wivF.x, hi ? biaF.y : biaF.x);
                float gG = D[2][p] + fmaf(xs, hi ? wivG.y : wivG.x, hi ? biaG.y : biaG.x);
                float gO = D[3][p] + fmaf(xs, hi ? wivO.y : wivO.x, hi ? biaO.y : biaO.x);
                float iv = sigf(gI);
                float fv = sigf(gF);
                float gv = tanhacc(gG);
                float ov = sigf(gO);
                float cn = fmaf(fv, c[jg * 4 + p], iv * gv);
                c[jg * 4 + p] = cn;
                hv[p] = ov * tanhacc(cn);
            }

            if (s < TSTEPS - 1) {
                // pack h into next step's A fragments (D layout == A layout)
                const int kk = jg >> 1;
                const int fo = (jg & 1) * 2;
                float h0h = __half2float(__float2half_rn(hv[0]));
                float h1h = __half2float(__float2half_rn(hv[1]));
                float h2h = __half2float(__float2half_rn(hv[2]));
                float h3h = __half2float(__float2half_rn(hv[3]));
                Ahi[wr][kk][fo + 0] = packh2(h0h, h1h);          // row gid
                Ahi[wr][kk][fo + 1] = packh2(h2h, h3h);          // row gid+8
                Alo[wr][kk][fo + 0] = packh2(hv[0] - h0h, hv[1] - h1h);
                Alo[wr][kk][fo + 1] = packh2(hv[2] - h2h, hv[3] - h3h);
            } else {
                float2 wf = *(const float2*)(wfc_s + cb);
                oacc0 = fmaf(hv[0], wf.x, fmaf(hv[1], wf.y, oacc0));
                oacc1 = fmaf(hv[2], wf.x, fmaf(hv[3], wf.y, oacc1));
            }
        }
    }

    // ---- head: reduce over the 4 tig lanes sharing each row ----
    oacc0 += __shfl_xor_sync(0xffffffffu, oacc0, 1);
    oacc0 += __shfl_xor_sync(0xffffffffu, oacc0, 2);
    oacc1 += __shfl_xor_sync(0xffffffffu, oacc1, 1);
    oacc1 += __shfl_xor_sync(0xffffffffu, oacc1, 2);
    if (tig == 0) {
        int g0 = blockIdx.x * MT + row0;
        int g1 = blockIdx.x * MT + row1;
        if (g0 < B) out[g0] = oacc0 + bfc;
        if (g1 < B) out[g1] = oacc1 + bfc;
    }
}

extern "C" void kernel_launch(void* const* d_in, const int* in_sizes, int n_in,
                              void* d_out, int out_size) {
    const float* x    = (const float*)d_in[0];
    const float* W_ih = (const float*)d_in[1];
    const float* W_hh = (const float*)d_in[2];
    const float* b_ih = (const float*)d_in[3];
    const float* b_hh = (const float*)d_in[4];
    const float* W_fc = (const float*)d_in[5];
    const float* b_fc = (const float*)d_in[6];
    float* out = (float*)d_out;

    const int B = in_sizes[0] / TSTEPS;
    const int grid = (B + MT - 1) / MT;

    cudaFuncSetAttribute(lstm_mma_kernel,
                         cudaFuncAttributeMaxDynamicSharedMemorySize, SM_SIZE);
    lstm_mma_kernel<<<grid, NTH, SM_SIZE>>>(x, W_ih, W_hh, b_ih, b_hh,
                                            W_fc, b_fc, out, B);
}

// round 5
// speedup vs baseline: 5.6962x; 5.6962x over previous
#include <cuda_runtime.h>
#include <cuda_fp16.h>

// WaterLevelLSTM via mma.sync.m16n8k16 (f16 -> f32), 3-term fp16 split.
// R5: kill R4's register spills. A fragments single-buffered in SMEM per
// warp (epilogue STS -> next-step ldmatrix, warp-private, __syncwarp only).
// c in 32 regs. 2 CTAs/SM (16 warps) via launch_bounds(256,2) + smem diet.

#define TSTEPS 5
#define NTH    256
#define MT     128
#define ROWPAD 72            // halves per row (144B = 9*16B, odd -> ldsm conflict-free)

// smem byte offsets
#define SM_WHI  0            // 256*72*2 = 36864
#define SM_WLO  36864        // 36864
#define SM_A    73728        // per-warp: hi 16*72*2=2304; lo at +18432; total 36864
#define SM_ALO_REL 18432
#define SM_BIAS 110592       // 256 floats
#define SM_WIH  111616       // 256 floats
#define SM_WFC  112640       // 64 floats
#define SM_SIZE 112896

typedef unsigned int u32;

__device__ __forceinline__ void mma16816(float* d, const u32* a, const u32* b) {
    asm volatile("mma.sync.aligned.m16n8k16.row.col.f32.f16.f16.f32 "
        "{%0,%1,%2,%3}, {%4,%5,%6,%7}, {%8,%9}, {%0,%1,%2,%3};"
        : "+f"(d[0]), "+f"(d[1]), "+f"(d[2]), "+f"(d[3])
        : "r"(a[0]), "r"(a[1]), "r"(a[2]), "r"(a[3]), "r"(b[0]), "r"(b[1]));
}
__device__ __forceinline__ void ldsm4(u32* r, u32 addr) {
    asm volatile("ldmatrix.sync.aligned.m8n8.x4.shared.b16 {%0,%1,%2,%3}, [%4];"
        : "=r"(r[0]), "=r"(r[1]), "=r"(r[2]), "=r"(r[3]) : "r"(addr));
}
__device__ __forceinline__ u32 s2u(const void* p) {
    u32 a;
    asm("{ .reg .u64 t; cvta.to.shared.u64 t, %1; cvt.u32.u64 %0, t; }"
        : "=r"(a) : "l"(p));
    return a;
}
__device__ __forceinline__ u32 packh2(float a, float b) {
    __half2 h = __floats2half2_rn(a, b);
    return *reinterpret_cast<u32*>(&h);
}
__device__ __forceinline__ void sts32(u32 addr, u32 v) {
    asm volatile("st.shared.b32 [%0], %1;" :: "r"(addr), "r"(v) : "memory");
}
// accurate MUFU sigmoid/tanh (EX2 ~2^-22), not tanh.approx
__device__ __forceinline__ float sigf(float x) {
    return __fdividef(1.0f, 1.0f + __expf(-x));
}
__device__ __forceinline__ float tanhacc(float x) {
    return __fdividef(2.0f, 1.0f + __expf(-2.0f * x)) - 1.0f;
}

__global__ __launch_bounds__(NTH, 2)
void lstm_mma_kernel(const float* __restrict__ x,
                     const float* __restrict__ W_ih,
                     const float* __restrict__ W_hh,
                     const float* __restrict__ b_ih,
                     const float* __restrict__ b_hh,
                     const float* __restrict__ W_fc,
                     const float* __restrict__ b_fc,
                     float* __restrict__ out,
                     int B)
{
    extern __shared__ char smem[];
    const u32 sb = s2u(smem);
    const int tid  = threadIdx.x;
    const int warp = tid >> 5;
    const int lane = tid & 31;
    const int gid  = lane >> 2;      // row group in warp tile
    const int tig  = lane & 3;       // col group

    __half* whi = reinterpret_cast<__half*>(smem + SM_WHI);
    __half* wlo = reinterpret_cast<__half*>(smem + SM_WLO);
    float* bias_s = reinterpret_cast<float*>(smem + SM_BIAS);
    float* wih_s  = reinterpret_cast<float*>(smem + SM_WIH);
    float* wfc_s  = reinterpret_cast<float*>(smem + SM_WFC);

    // ---- prologue: split W_hh to fp16 hi/lo; stage biases ----
    for (int i = tid; i < 256 * 64; i += NTH) {
        int n = i >> 6, k = i & 63;
        float w  = W_hh[i];
        __half hh = __float2half_rn(w);
        whi[n * ROWPAD + k] = hh;
        wlo[n * ROWPAD + k] = __float2half_rn(w - __half2float(hh));
    }
    if (tid < 256) {
        bias_s[tid] = b_ih[tid] + b_hh[tid];
        wih_s[tid]  = W_ih[tid];
    }
    if (tid < 64) wfc_s[tid] = W_fc[tid];
    __syncthreads();   // only block-wide sync

    // ---- per-thread setup ----
    const int row0 = warp * 16 + gid;
    const int row1 = row0 + 8;
    const long g0 = (long)blockIdx.x * MT + row0;
    const long g1 = (long)blockIdx.x * MT + row1;
    const bool v0 = g0 < B, v1 = g1 < B;
    const float bfc = b_fc[0];

    const u32 a_hi = sb + SM_A + (u32)warp * 2304u;
    const u32 a_lo = a_hi + SM_ALO_REL;
    const u32 whi_b = sb + SM_WHI;
    const u32 lmoffB = (u32)((lane & 7) * (ROWPAD * 2) + (lane >> 3) * 16);
    const u32 lmoffA = (u32)((lane & 15) * (ROWPAD * 2) + (lane >> 4) * 16);

    float c[32];
#pragma unroll
    for (int i = 0; i < 32; i++) c[i] = 0.0f;
    float oacc0 = 0.0f, oacc1 = 0.0f;

#pragma unroll
    for (int s = 0; s < TSTEPS; s++) {
        // x for this step (tiny, L2-cached)
        const float xs0 = v0 ? __ldg(x + g0 * TSTEPS + s) : 0.0f;
        const float xs1 = v1 ? __ldg(x + g1 * TSTEPS + s) : 0.0f;

        u32 Ahi[4][4], Alo[4][4];
        if (s > 0) {
#pragma unroll
            for (int kc = 0; kc < 4; kc++) {
                ldsm4(Ahi[kc], a_hi + (u32)kc * 32u + lmoffA);
                ldsm4(Alo[kc], a_lo + (u32)kc * 32u + lmoffA);
            }
        }

#pragma unroll
        for (int jg = 0; jg < 8; jg++) {
            float D[4][4];
#pragma unroll
            for (int ty = 0; ty < 4; ty++)
#pragma unroll
                for (int p = 0; p < 4; p++) D[ty][p] = 0.0f;

            if (s > 0) {
#pragma unroll
                for (int ty = 0; ty < 4; ty++) {
                    u32 rb = whi_b + (u32)((ty * 64 + jg * 8) * (ROWPAD * 2)) + lmoffB;
                    u32 bh[8], bl[8];
                    ldsm4(bh + 0, rb);                // W_hi k[0,32)
                    ldsm4(bh + 4, rb + 64);           // W_hi k[32,64)
                    ldsm4(bl + 0, rb + 36864);        // W_lo
                    ldsm4(bl + 4, rb + 36864 + 64);
#pragma unroll
                    for (int kk = 0; kk < 4; kk++) {
                        mma16816(D[ty], Ahi[kk], bh + 2 * kk);
                        mma16816(D[ty], Alo[kk], bh + 2 * kk);
                        mma16816(D[ty], Ahi[kk], bl + 2 * kk);
                    }
                }
            }

            // ---- epilogue: 4 units (2 rows x 2 cols) ----
            const int cb = jg * 8 + 2 * tig;
            float2 biaI = *(const float2*)(bias_s + 0 * 64 + cb);
            float2 biaF = *(const float2*)(bias_s + 1 * 64 + cb);
            float2 biaG = *(const float2*)(bias_s + 2 * 64 + cb);
            float2 biaO = *(const float2*)(bias_s + 3 * 64 + cb);
            float2 wivI = *(const float2*)(wih_s + 0 * 64 + cb);
            float2 wivF = *(const float2*)(wih_s + 1 * 64 + cb);
            float2 wivG = *(const float2*)(wih_s + 2 * 64 + cb);
            float2 wivO = *(const float2*)(wih_s + 3 * 64 + cb);

            float hv[4];
#pragma unroll
            for (int p = 0; p < 4; p++) {
                const float xs = (p < 2) ? xs0 : xs1;
                const bool hi = (p & 1);
                float gI = D[0][p] + fmaf(xs, hi ? wivI.y : wivI.x, hi ? biaI.y : biaI.x);
                float gF = D[1][p] + fmaf(xs, hi ? wivF.y : wivF.x, hi ? biaF.y : biaF.x);
                float gG = D[2][p] + fmaf(xs, hi ? wivG.y : wivG.x, hi ? biaG.y : biaG.x);
                float gO = D[3][p] + fmaf(xs, hi ? wivO.y : wivO.x, hi ? biaO.y : biaO.x);
                float iv = sigf(gI);
                float fv = sigf(gF);
                float gv = tanhacc(gG);
                float ov = sigf(gO);
                float cn = fmaf(fv, c[jg * 4 + p], iv * gv);
                c[jg * 4 + p] = cn;
                hv[p] = ov * tanhacc(cn);
            }

            if (s < TSTEPS - 1) {
                // store new h (hi/lo fp16) into this warp's A staging region
                float h0h = __half2float(__float2half_rn(hv[0]));
                float h1h = __half2float(__float2half_rn(hv[1]));
                float h2h = __half2float(__float2half_rn(hv[2]));
                float h3h = __half2float(__float2half_rn(hv[3]));
                u32 off = (u32)((gid * ROWPAD + cb) * 2);
                sts32(a_hi + off,                    packh2(h0h, h1h));          // row gid
                sts32(a_hi + off + 8 * ROWPAD * 2,   packh2(h2h, h3h));          // row gid+8
                sts32(a_lo + off,                    packh2(hv[0] - h0h, hv[1] - h1h));
                sts32(a_lo + off + 8 * ROWPAD * 2,   packh2(hv[2] - h2h, hv[3] - h3h));
            } else {
                float2 wf = *(const float2*)(wfc_s + cb);
                oacc0 = fmaf(hv[0], wf.x, fmaf(hv[1], wf.y, oacc0));
                oacc1 = fmaf(hv[2], wf.x, fmaf(hv[3], wf.y, oacc1));
            }
        }
        __syncwarp();   // h stores visible to whole warp before next ldsm
    }

    // ---- head: reduce over the 4 tig lanes sharing each row ----
    oacc0 += __shfl_xor_sync(0xffffffffu, oacc0, 1);
    oacc0 += __shfl_xor_sync(0xffffffffu, oacc0, 2);
    oacc1 += __shfl_xor_sync(0xffffffffu, oacc1, 1);
    oacc1 += __shfl_xor_sync(0xffffffffu, oacc1, 2);
    if (tig == 0) {
        if (v0) out[g0] = oacc0 + bfc;
        if (v1) out[g1] = oacc1 + bfc;
    }
}

extern "C" void kernel_launch(void* const* d_in, const int* in_sizes, int n_in,
                              void* d_out, int out_size) {
    const float* x    = (const float*)d_in[0];
    const float* W_ih = (const float*)d_in[1];
    const float* W_hh = (const float*)d_in[2];
    const float* b_ih = (const float*)d_in[3];
    const float* b_hh = (const float*)d_in[4];
    const float* W_fc = (const float*)d_in[5];
    const float* b_fc = (const float*)d_in[6];
    float* out = (float*)d_out;

    const int B = in_sizes[0] / TSTEPS;
    const int grid = (B + MT - 1) / MT;

    cudaFuncSetAttribute(lstm_mma_kernel,
                         cudaFuncAttributeMaxDynamicSharedMemorySize, SM_SIZE);
    lstm_mma_kernel<<<grid, NTH, SM_SIZE>>>(x, W_ih, W_hh, b_ih, b_hh,
                                            W_fc, b_fc, out, B);
}

// round 6
// speedup vs baseline: 6.9173x; 1.2144x over previous
#include <cuda_runtime.h>
#include <cuda_fp16.h>

// WaterLevelLSTM via mma.sync.m16n8k16 (f16 -> f32).
// R6: 2-term split (h_hi*W_hi + h_lo*W_hi; W kept as single fp16 table).
// Tensor work -33%, B-ldmatrix traffic -50%, epilogue bias loads packed
// as float4. MUFU (accurate sigmoid/tanh) is now the target ceiling.

#define TSTEPS 5
#define NTH    256
#define MT     128
#define ROWPAD 72            // halves per row (144B) -> ldsm conflict-free

// smem byte offsets
#define SM_WHI  0            // 256*72*2 = 36864
#define SM_A    36864        // 8 warps x (hi 2304 | lo 2304) = 36864
#define SM_ALO_REL 18432
#define SM_BC   73728        // [8 jg][4 tig][4 float4] = 2048 (bias+wih)
#define SM_WFC  75776        // 64 floats
#define SM_SIZE 76032

typedef unsigned int u32;

__device__ __forceinline__ void mma16816(float* d, const u32* a, const u32* b) {
    asm volatile("mma.sync.aligned.m16n8k16.row.col.f32.f16.f16.f32 "
        "{%0,%1,%2,%3}, {%4,%5,%6,%7}, {%8,%9}, {%0,%1,%2,%3};"
        : "+f"(d[0]), "+f"(d[1]), "+f"(d[2]), "+f"(d[3])
        : "r"(a[0]), "r"(a[1]), "r"(a[2]), "r"(a[3]), "r"(b[0]), "r"(b[1]));
}
__device__ __forceinline__ void ldsm4(u32* r, u32 addr) {
    asm volatile("ldmatrix.sync.aligned.m8n8.x4.shared.b16 {%0,%1,%2,%3}, [%4];"
        : "=r"(r[0]), "=r"(r[1]), "=r"(r[2]), "=r"(r[3]) : "r"(addr));
}
__device__ __forceinline__ u32 s2u(const void* p) {
    u32 a;
    asm("{ .reg .u64 t; cvta.to.shared.u64 t, %1; cvt.u32.u64 %0, t; }"
        : "=r"(a) : "l"(p));
    return a;
}
__device__ __forceinline__ u32 packh2(float a, float b) {
    __half2 h = __floats2half2_rn(a, b);
    return *reinterpret_cast<u32*>(&h);
}
__device__ __forceinline__ void sts32(u32 addr, u32 v) {
    asm volatile("st.shared.b32 [%0], %1;" :: "r"(addr), "r"(v) : "memory");
}
// accurate MUFU sigmoid/tanh (EX2 ~2^-22), not tanh.approx
__device__ __forceinline__ float sigf(float x) {
    return __fdividef(1.0f, 1.0f + __expf(-x));
}
__device__ __forceinline__ float tanhacc(float x) {
    return __fdividef(2.0f, 1.0f + __expf(-2.0f * x)) - 1.0f;
}

__global__ __launch_bounds__(NTH, 2)
void lstm_mma_kernel(const float* __restrict__ x,
                     const float* __restrict__ W_ih,
                     const float* __restrict__ W_hh,
                     const float* __restrict__ b_ih,
                     const float* __restrict__ b_hh,
                     const float* __restrict__ W_fc,
                     const float* __restrict__ b_fc,
                     float* __restrict__ out,
                     int B)
{
    extern __shared__ char smem[];
    const u32 sb = s2u(smem);
    const int tid  = threadIdx.x;
    const int warp = tid >> 5;
    const int lane = tid & 31;
    const int gid  = lane >> 2;      // row group in warp tile
    const int tig  = lane & 3;       // col group

    __half* whi  = reinterpret_cast<__half*>(smem + SM_WHI);
    float*  bc_s = reinterpret_cast<float*>(smem + SM_BC);
    float*  wfc_s = reinterpret_cast<float*>(smem + SM_WFC);

    // ---- prologue: W_hh -> fp16 table; pack bias/wih by (jg,tig,col,type) ----
    for (int i = tid; i < 256 * 64; i += NTH) {
        int n = i >> 6, k = i & 63;
        whi[n * ROWPAD + k] = __float2half_rn(W_hh[i]);
    }
    if (tid < 256) {
        int type = tid >> 6, j = tid & 63;
        int jg = j >> 3, tg = (j >> 1) & 3, col = j & 1;
        int base = (jg * 4 + tg) * 16 + col * 4 + type;
        bc_s[base]     = b_ih[tid] + b_hh[tid];
        bc_s[base + 8] = W_ih[tid];
    }
    if (tid < 64) wfc_s[tid] = W_fc[tid];
    __syncthreads();   // only block-wide sync

    // ---- per-thread setup ----
    const int row0 = warp * 16 + gid;
    const int row1 = row0 + 8;
    const long g0 = (long)blockIdx.x * MT + row0;
    const long g1 = (long)blockIdx.x * MT + row1;
    const bool v0 = g0 < B, v1 = g1 < B;
    const float bfc = b_fc[0];

    float xv0[TSTEPS], xv1[TSTEPS];
#pragma unroll
    for (int s = 0; s < TSTEPS; s++) {
        xv0[s] = v0 ? __ldg(x + g0 * TSTEPS + s) : 0.0f;
        xv1[s] = v1 ? __ldg(x + g1 * TSTEPS + s) : 0.0f;
    }

    const u32 a_hi = sb + SM_A + (u32)warp * 2304u;
    const u32 a_lo = a_hi + SM_ALO_REL;
    const u32 whi_b = sb + SM_WHI;
    const u32 lmoffB = (u32)((lane & 7) * (ROWPAD * 2) + (lane >> 3) * 16);
    const u32 lmoffA = (u32)((lane & 15) * (ROWPAD * 2) + (lane >> 4) * 16);

    float c[32];
#pragma unroll
    for (int i = 0; i < 32; i++) c[i] = 0.0f;
    float oacc0 = 0.0f, oacc1 = 0.0f;

#pragma unroll
    for (int s = 0; s < TSTEPS; s++) {
        u32 Ahi[4][4], Alo[4][4];
        if (s > 0) {
#pragma unroll
            for (int kc = 0; kc < 4; kc++) {
                ldsm4(Ahi[kc], a_hi + (u32)kc * 32u + lmoffA);
                ldsm4(Alo[kc], a_lo + (u32)kc * 32u + lmoffA);
            }
        }
        const float xs0 = xv0[s], xs1 = xv1[s];

#pragma unroll
        for (int jg = 0; jg < 8; jg++) {
            float D[4][4];
#pragma unroll
            for (int ty = 0; ty < 4; ty++)
#pragma unroll
                for (int p = 0; p < 4; p++) D[ty][p] = 0.0f;

            if (s > 0) {
#pragma unroll
                for (int ty = 0; ty < 4; ty++) {
                    u32 rb = whi_b + (u32)((ty * 64 + jg * 8) * (ROWPAD * 2)) + lmoffB;
                    u32 bh[8];
                    ldsm4(bh + 0, rb);          // W_hi k[0,32)
                    ldsm4(bh + 4, rb + 64);     // W_hi k[32,64)
#pragma unroll
                    for (int kk = 0; kk < 4; kk++) {
                        mma16816(D[ty], Ahi[kk], bh + 2 * kk);
                        mma16816(D[ty], Alo[kk], bh + 2 * kk);
                    }
                }
            }

            // ---- epilogue: 4 units (2 rows x 2 cols) ----
            const float4* bc = reinterpret_cast<const float4*>(bc_s)
                               + (jg * 4 + tig) * 4;
            float4 b0 = bc[0];   // bias col0 {i,f,g,o}
            float4 b1 = bc[1];   // bias col1
            float4 w0 = bc[2];   // wih  col0
            float4 w1 = bc[3];   // wih  col1

            float hv[4];
#pragma unroll
            for (int p = 0; p < 4; p++) {
                const float xs = (p < 2) ? xs0 : xs1;
                const bool hi = (p & 1);
                const float4 bb = hi ? b1 : b0;
                const float4 ww = hi ? w1 : w0;
                float gI = D[0][p] + fmaf(xs, ww.x, bb.x);
                float gF = D[1][p] + fmaf(xs, ww.y, bb.y);
                float gG = D[2][p] + fmaf(xs, ww.z, bb.z);
                float gO = D[3][p] + fmaf(xs, ww.w, bb.w);
                float iv = sigf(gI);
                float fv = sigf(gF);
                float gv = tanhacc(gG);
                float ov = sigf(gO);
                float cn = fmaf(fv, c[jg * 4 + p], iv * gv);
                c[jg * 4 + p] = cn;
                hv[p] = ov * tanhacc(cn);
            }

            if (s < TSTEPS - 1) {
                // stage new h (hi/lo fp16) for next step's A
                float h0h = __half2float(__float2half_rn(hv[0]));
                float h1h = __half2float(__float2half_rn(hv[1]));
                float h2h = __half2float(__float2half_rn(hv[2]));
                float h3h = __half2float(__float2half_rn(hv[3]));
                const int cb = jg * 8 + 2 * tig;
                u32 off = (u32)((gid * ROWPAD + cb) * 2);
                sts32(a_hi + off,                  packh2(h0h, h1h));
                sts32(a_hi + off + 8 * ROWPAD * 2, packh2(h2h, h3h));
                sts32(a_lo + off,                  packh2(hv[0] - h0h, hv[1] - h1h));
                sts32(a_lo + off + 8 * ROWPAD * 2, packh2(hv[2] - h2h, hv[3] - h3h));
            } else {
                const int cb = jg * 8 + 2 * tig;
                float2 wf = *(const float2*)(wfc_s + cb);
                oacc0 = fmaf(hv[0], wf.x, fmaf(hv[1], wf.y, oacc0));
                oacc1 = fmaf(hv[2], wf.x, fmaf(hv[3], wf.y, oacc1));
            }
        }
        __syncwarp();   // h stores visible warp-wide before next ldsm
    }

    // ---- head: reduce over the 4 tig lanes sharing each row ----
    oacc0 += __shfl_xor_sync(0xffffffffu, oacc0, 1);
    oacc0 += __shfl_xor_sync(0xffffffffu, oacc0, 2);
    oacc1 += __shfl_xor_sync(0xffffffffu, oacc1, 1);
    oacc1 += __shfl_xor_sync(0xffffffffu, oacc1, 2);
    if (tig == 0) {
        if (v0) out[g0] = oacc0 + bfc;
        if (v1) out[g1] = oacc1 + bfc;
    }
}

extern "C" void kernel_launch(void* const* d_in, const int* in_sizes, int n_in,
                              void* d_out, int out_size) {
    const float* x    = (const float*)d_in[0];
    const float* W_ih = (const float*)d_in[1];
    const float* W_hh = (const float*)d_in[2];
    const float* b_ih = (const float*)d_in[3];
    const float* b_hh = (const float*)d_in[4];
    const float* W_fc = (const float*)d_in[5];
    const float* b_fc = (const float*)d_in[6];
    float* out = (float*)d_out;

    const int B = in_sizes[0] / TSTEPS;
    const int grid = (B + MT - 1) / MT;

    cudaFuncSetAttribute(lstm_mma_kernel,
                         cudaFuncAttributeMaxDynamicSharedMemorySize, SM_SIZE);
    lstm_mma_kernel<<<grid, NTH, SM_SIZE>>>(x, W_ih, W_hh, b_ih, b_hh,
                                            W_fc, b_fc, out, B);
}

// round 7
// speedup vs baseline: 8.9861x; 1.2991x over previous
#include <cuda_runtime.h>
#include <cuda_fp16.h>

// WaterLevelLSTM via mma.sync.m16n8k16 (f16 -> f32), 2-term h split.
// R7: activations on the hardware MUFU.TANH (tanh.approx.f32).
//   tanh(x)    = tanh.approx(x)                      (1 MUFU)
//   sigmoid(x) = 0.5 * tanh.approx(0.5x) + 0.5       (1 MUFU + 2 FMA)
// Halves MUFU issue count and chain latency vs the EX2+RCP versions.

#define TSTEPS 5
#define NTH    256
#define MT     128
#define ROWPAD 72            // halves per row (144B) -> ldsm conflict-free

// smem byte offsets
#define SM_WHI  0            // 256*72*2 = 36864
#define SM_A    36864        // 8 warps x (hi 2304 | lo 2304) = 36864
#define SM_ALO_REL 18432
#define SM_BC   73728        // [8 jg][4 tig][4 float4] = 2048 (bias+wih)
#define SM_WFC  75776        // 64 floats
#define SM_SIZE 76032

typedef unsigned int u32;

__device__ __forceinline__ void mma16816(float* d, const u32* a, const u32* b) {
    asm volatile("mma.sync.aligned.m16n8k16.row.col.f32.f16.f16.f32 "
        "{%0,%1,%2,%3}, {%4,%5,%6,%7}, {%8,%9}, {%0,%1,%2,%3};"
        : "+f"(d[0]), "+f"(d[1]), "+f"(d[2]), "+f"(d[3])
        : "r"(a[0]), "r"(a[1]), "r"(a[2]), "r"(a[3]), "r"(b[0]), "r"(b[1]));
}
__device__ __forceinline__ void ldsm4(u32* r, u32 addr) {
    asm volatile("ldmatrix.sync.aligned.m8n8.x4.shared.b16 {%0,%1,%2,%3}, [%4];"
        : "=r"(r[0]), "=r"(r[1]), "=r"(r[2]), "=r"(r[3]) : "r"(addr));
}
__device__ __forceinline__ u32 s2u(const void* p) {
    u32 a;
    asm("{ .reg .u64 t; cvta.to.shared.u64 t, %1; cvt.u32.u64 %0, t; }"
        : "=r"(a) : "l"(p));
    return a;
}
__device__ __forceinline__ u32 packh2(float a, float b) {
    __half2 h = __floats2half2_rn(a, b);
    return *reinterpret_cast<u32*>(&h);
}
__device__ __forceinline__ void sts32(u32 addr, u32 v) {
    asm volatile("st.shared.b32 [%0], %1;" :: "r"(addr), "r"(v) : "memory");
}
// hardware tanh (MUFU.TANH, sm_75+): 1 MUFU op
__device__ __forceinline__ float tanh_hw(float x) {
    float r;
    asm("tanh.approx.f32 %0, %1;" : "=f"(r) : "f"(x));
    return r;
}
__device__ __forceinline__ float sigf(float x) {
    return fmaf(tanh_hw(0.5f * x), 0.5f, 0.5f);
}

__global__ __launch_bounds__(NTH, 2)
void lstm_mma_kernel(const float* __restrict__ x,
                     const float* __restrict__ W_ih,
                     const float* __restrict__ W_hh,
                     const float* __restrict__ b_ih,
                     const float* __restrict__ b_hh,
                     const float* __restrict__ W_fc,
                     const float* __restrict__ b_fc,
                     float* __restrict__ out,
                     int B)
{
    extern __shared__ char smem[];
    const u32 sb = s2u(smem);
    const int tid  = threadIdx.x;
    const int warp = tid >> 5;
    const int lane = tid & 31;
    const int gid  = lane >> 2;      // row group in warp tile
    const int tig  = lane & 3;       // col group

    __half* whi  = reinterpret_cast<__half*>(smem + SM_WHI);
    float*  bc_s = reinterpret_cast<float*>(smem + SM_BC);
    float*  wfc_s = reinterpret_cast<float*>(smem + SM_WFC);

    // ---- prologue: W_hh -> fp16 table; pack bias/wih by (jg,tig,col,type) ----
    for (int i = tid; i < 256 * 64; i += NTH) {
        int n = i >> 6, k = i & 63;
        whi[n * ROWPAD + k] = __float2half_rn(W_hh[i]);
    }
    if (tid < 256) {
        int type = tid >> 6, j = tid & 63;
        int jg = j >> 3, tg = (j >> 1) & 3, col = j & 1;
        int base = (jg * 4 + tg) * 16 + col * 4 + type;
        bc_s[base]     = b_ih[tid] + b_hh[tid];
        bc_s[base + 8] = W_ih[tid];
    }
    if (tid < 64) wfc_s[tid] = W_fc[tid];
    __syncthreads();   // only block-wide sync

    // ---- per-thread setup ----
    const int row0 = warp * 16 + gid;
    const int row1 = row0 + 8;
    const long g0 = (long)blockIdx.x * MT + row0;
    const long g1 = (long)blockIdx.x * MT + row1;
    const bool v0 = g0 < B, v1 = g1 < B;
    const float bfc = b_fc[0];

    float xv0[TSTEPS], xv1[TSTEPS];
#pragma unroll
    for (int s = 0; s < TSTEPS; s++) {
        xv0[s] = v0 ? __ldg(x + g0 * TSTEPS + s) : 0.0f;
        xv1[s] = v1 ? __ldg(x + g1 * TSTEPS + s) : 0.0f;
    }

    const u32 a_hi = sb + SM_A + (u32)warp * 2304u;
    const u32 a_lo = a_hi + SM_ALO_REL;
    const u32 whi_b = sb + SM_WHI;
    const u32 lmoffB = (u32)((lane & 7) * (ROWPAD * 2) + (lane >> 3) * 16);
    const u32 lmoffA = (u32)((lane & 15) * (ROWPAD * 2) + (lane >> 4) * 16);

    float c[32];
#pragma unroll
    for (int i = 0; i < 32; i++) c[i] = 0.0f;
    float oacc0 = 0.0f, oacc1 = 0.0f;

#pragma unroll
    for (int s = 0; s < TSTEPS; s++) {
        u32 Ahi[4][4], Alo[4][4];
        if (s > 0) {
#pragma unroll
            for (int kc = 0; kc < 4; kc++) {
                ldsm4(Ahi[kc], a_hi + (u32)kc * 32u + lmoffA);
                ldsm4(Alo[kc], a_lo + (u32)kc * 32u + lmoffA);
            }
        }
        const float xs0 = xv0[s], xs1 = xv1[s];

#pragma unroll
        for (int jg = 0; jg < 8; jg++) {
            float D[4][4];
#pragma unroll
            for (int ty = 0; ty < 4; ty++)
#pragma unroll
                for (int p = 0; p < 4; p++) D[ty][p] = 0.0f;

            if (s > 0) {
#pragma unroll
                for (int ty = 0; ty < 4; ty++) {
                    u32 rb = whi_b + (u32)((ty * 64 + jg * 8) * (ROWPAD * 2)) + lmoffB;
                    u32 bh[8];
                    ldsm4(bh + 0, rb);          // W_hi k[0,32)
                    ldsm4(bh + 4, rb + 64);     // W_hi k[32,64)
#pragma unroll
                    for (int kk = 0; kk < 4; kk++) {
                        mma16816(D[ty], Ahi[kk], bh + 2 * kk);
                        mma16816(D[ty], Alo[kk], bh + 2 * kk);
                    }
                }
            }

            // ---- epilogue: 4 units (2 rows x 2 cols) ----
            const float4* bc = reinterpret_cast<const float4*>(bc_s)
                               + (jg * 4 + tig) * 4;
            float4 b0 = bc[0];   // bias col0 {i,f,g,o}
            float4 b1 = bc[1];   // bias col1
            float4 w0 = bc[2];   // wih  col0
            float4 w1 = bc[3];   // wih  col1

            float hv[4];
#pragma unroll
            for (int p = 0; p < 4; p++) {
                const float xs = (p < 2) ? xs0 : xs1;
                const bool hi = (p & 1);
                const float4 bb = hi ? b1 : b0;
                const float4 ww = hi ? w1 : w0;
                float gI = D[0][p] + fmaf(xs, ww.x, bb.x);
                float gF = D[1][p] + fmaf(xs, ww.y, bb.y);
                float gG = D[2][p] + fmaf(xs, ww.z, bb.z);
                float gO = D[3][p] + fmaf(xs, ww.w, bb.w);
                float iv = sigf(gI);
                float fv = sigf(gF);
                float gv = tanh_hw(gG);
                float ov = sigf(gO);
                float cn = fmaf(fv, c[jg * 4 + p], iv * gv);
                c[jg * 4 + p] = cn;
                hv[p] = ov * tanh_hw(cn);
            }

            if (s < TSTEPS - 1) {
                // stage new h (hi/lo fp16) for next step's A
                float h0h = __half2float(__float2half_rn(hv[0]));
                float h1h = __half2float(__float2half_rn(hv[1]));
                float h2h = __half2float(__float2half_rn(hv[2]));
                float h3h = __half2float(__float2half_rn(hv[3]));
                const int cb = jg * 8 + 2 * tig;
                u32 off = (u32)((gid * ROWPAD + cb) * 2);
                sts32(a_hi + off,                  packh2(h0h, h1h));
                sts32(a_hi + off + 8 * ROWPAD * 2, packh2(h2h, h3h));
                sts32(a_lo + off,                  packh2(hv[0] - h0h, hv[1] - h1h));
                sts32(a_lo + off + 8 * ROWPAD * 2, packh2(hv[2] - h2h, hv[3] - h3h));
            } else {
                const int cb = jg * 8 + 2 * tig;
                float2 wf = *(const float2*)(wfc_s + cb);
                oacc0 = fmaf(hv[0], wf.x, fmaf(hv[1], wf.y, oacc0));
                oacc1 = fmaf(hv[2], wf.x, fmaf(hv[3], wf.y, oacc1));
            }
        }
        __syncwarp();   // h stores visible warp-wide before next ldsm
    }

    // ---- head: reduce over the 4 tig lanes sharing each row ----
    oacc0 += __shfl_xor_sync(0xffffffffu, oacc0, 1);
    oacc0 += __shfl_xor_sync(0xffffffffu, oacc0, 2);
    oacc1 += __shfl_xor_sync(0xffffffffu, oacc1, 1);
    oacc1 += __shfl_xor_sync(0xffffffffu, oacc1, 2);
    if (tig == 0) {
        if (v0) out[g0] = oacc0 + bfc;
        if (v1) out[g1] = oacc1 + bfc;
    }
}

extern "C" void kernel_launch(void* const* d_in, const int* in_sizes, int n_in,
                              void* d_out, int out_size) {
    const float* x    = (const float*)d_in[0];
    const float* W_ih = (const float*)d_in[1];
    const float* W_hh = (const float*)d_in[2];
    const float* b_ih = (const float*)d_in[3];
    const float* b_hh = (const float*)d_in[4];
    const float* W_fc = (const float*)d_in[5];
    const float* b_fc = (const float*)d_in[6];
    float* out = (float*)d_out;

    const int B = in_sizes[0] / TSTEPS;
    const int grid = (B + MT - 1) / MT;

    cudaFuncSetAttribute(lstm_mma_kernel,
                         cudaFuncAttributeMaxDynamicSharedMemorySize, SM_SIZE);
    lstm_mma_kernel<<<grid, NTH, SM_SIZE>>>(x, W_ih, W_hh, b_ih, b_hh,
                                            W_fc, b_fc, out, B);
}